// round 14
// baseline (speedup 1.0000x reference)
#include <cuda_runtime.h>

// Problem constants
#define T_STEPS 512
#define BATCH   512
#define IN0     64
#define H       128
#define G       512   // 4*H

// Scratch (rules: no cudaMalloc -> __device__ globals)
__device__ float g_P [(size_t)T_STEPS * BATCH * G];   // 512 MB, reused for both layers
__device__ float g_HS[(size_t)T_STEPS * BATCH * H];   // 128 MB, layer-0 hidden states
__device__ float g_HL[BATCH * H];                     // layer-1 last hidden state

typedef unsigned long long u64;

// ---- packed fp32x2 helpers ----
__device__ __forceinline__ u64 ffma2(u64 a, u64 b, u64 c) {
    u64 d;
    asm("fma.rn.f32x2 %0, %1, %2, %3;" : "=l"(d) : "l"(a), "l"(b), "l"(c));
    return d;
}
__device__ __forceinline__ u64 pk2(float lo, float hi) {
    u64 d; unsigned a = __float_as_uint(lo), b = __float_as_uint(hi);
    asm("mov.b64 %0, {%1, %2};" : "=l"(d) : "r"(a), "r"(b));
    return d;
}
__device__ __forceinline__ float hsum2(u64 v) {
    unsigned a, b;
    asm("mov.b64 {%0, %1}, %2;" : "=r"(a), "=r"(b) : "l"(v));
    return __uint_as_float(a) + __uint_as_float(b);
}

// ---- fast activations (MUFU EX2+RCP, ~1e-6 rel err) ----
__device__ __forceinline__ float sigm(float x) {
    return __fdividef(1.f, 1.f + __expf(-x));
}
__device__ __forceinline__ float tanh_f(float x) {
    return 2.f * sigm(2.f * x) - 1.f;
}

// ============================================================================
// proj0: P[t][b][n] = sum_k x[b][t][k] * W_ih0[n][k] + b_ih0[n] + b_hh0[n]
// v2: 256 threads, 2 gates/thread (n, n+256), weights fully in regs (128),
// 4-row accumulators -> each broadcast h LDS.128 feeds 4 FFMA2.
// FIX R13: inner loop j < 16 (64-float row = 16 ulonglong2, was 8 = half row).
// ============================================================================
__global__ void __launch_bounds__(256, 1)
proj0_kernel(const float* __restrict__ x, const float* __restrict__ Wih,
             const float* __restrict__ bih, const float* __restrict__ bhh)
{
    __shared__ float4 xs4[128 * 16];   // 128 rows x 64 floats = 32 KB
    const int n    = threadIdx.x;      // gates n and n+256
    const int row0 = blockIdx.x * 128;
    const int t    = row0 >> 9;        // 128 | 512 -> t constant per block
    const int b0   = row0 & 511;

    u64 wA[32], wB[32];                // 64 floats per gate, all in regs
    {
        const ulonglong2* WA2 = reinterpret_cast<const ulonglong2*>(Wih + n * IN0);
        const ulonglong2* WB2 = reinterpret_cast<const ulonglong2*>(Wih + (n + 256) * IN0);
        #pragma unroll
        for (int i = 0; i < 16; i++) {
            ulonglong2 v = WA2[i]; wA[2*i] = v.x; wA[2*i+1] = v.y;
            ulonglong2 u = WB2[i]; wB[2*i] = u.x; wB[2*i+1] = u.y;
        }
    }
    const float bnA = bih[n]       + bhh[n];
    const float bnB = bih[n + 256] + bhh[n + 256];

    // cooperative load of 128 x-rows (2048 float4)
    #pragma unroll
    for (int it = 0; it < 8; it++) {
        int i = n + it * 256;
        int r = i >> 4, c = i & 15;
        xs4[i] = reinterpret_cast<const float4*>(
                     x + ((size_t)(b0 + r) * T_STEPS + t) * IN0)[c];
    }
    __syncthreads();

    float* Pout = g_P + (size_t)row0 * G;
    #pragma unroll 1
    for (int r = 0; r < 128; r += 4) {
        u64 aA0 = pk2(bnA, 0.f), aA1 = pk2(bnA, 0.f), aA2 = pk2(bnA, 0.f), aA3 = pk2(bnA, 0.f);
        u64 aB0 = pk2(bnB, 0.f), aB1 = pk2(bnB, 0.f), aB2 = pk2(bnB, 0.f), aB3 = pk2(bnB, 0.f);
        const ulonglong2* h0 = reinterpret_cast<const ulonglong2*>(xs4 + (r+0)*16);
        const ulonglong2* h1 = reinterpret_cast<const ulonglong2*>(xs4 + (r+1)*16);
        const ulonglong2* h2 = reinterpret_cast<const ulonglong2*>(xs4 + (r+2)*16);
        const ulonglong2* h3 = reinterpret_cast<const ulonglong2*>(xs4 + (r+3)*16);
        #pragma unroll
        for (int j = 0; j < 16; j++) {   // FIX: 16 ulonglong2 = full 64-float row
            ulonglong2 a = h0[j], b = h1[j], c = h2[j], d = h3[j];
            u64 wa = wA[2*j], wb = wA[2*j+1], wc = wB[2*j], wd = wB[2*j+1];
            aA0 = ffma2(a.x, wa, aA0); aA0 = ffma2(a.y, wb, aA0);
            aA1 = ffma2(b.x, wa, aA1); aA1 = ffma2(b.y, wb, aA1);
            aA2 = ffma2(c.x, wa, aA2); aA2 = ffma2(c.y, wb, aA2);
            aA3 = ffma2(d.x, wa, aA3); aA3 = ffma2(d.y, wb, aA3);
            aB0 = ffma2(a.x, wc, aB0); aB0 = ffma2(a.y, wd, aB0);
            aB1 = ffma2(b.x, wc, aB1); aB1 = ffma2(b.y, wd, aB1);
            aB2 = ffma2(c.x, wc, aB2); aB2 = ffma2(c.y, wd, aB2);
            aB3 = ffma2(d.x, wc, aB3); aB3 = ffma2(d.y, wd, aB3);
        }
        Pout[(size_t)(r+0) * G + n] = hsum2(aA0);
        Pout[(size_t)(r+1) * G + n] = hsum2(aA1);
        Pout[(size_t)(r+2) * G + n] = hsum2(aA2);
        Pout[(size_t)(r+3) * G + n] = hsum2(aA3);
        Pout[(size_t)(r+0) * G + n + 256] = hsum2(aB0);
        Pout[(size_t)(r+1) * G + n + 256] = hsum2(aB1);
        Pout[(size_t)(r+2) * G + n + 256] = hsum2(aB2);
        Pout[(size_t)(r+3) * G + n + 256] = hsum2(aB3);
    }
}

// ============================================================================
// proj1: P[t][b][n] = sum_k HS[t][b][k] * W_ih1[n][k] + bias
// v2: 256 rows/block. 256 threads, 2 gates/thread, k<80 regs / [80,128) smem.
// ============================================================================
__global__ void __launch_bounds__(256, 1)
proj1_kernel(const float* __restrict__ Wih,
             const float* __restrict__ bih, const float* __restrict__ bhh)
{
    extern __shared__ char smp[];
    float4* sh4 = reinterpret_cast<float4*>(smp);              // 256x128 floats = 128 KB
    float4* Wp4 = reinterpret_cast<float4*>(smp + 131072);     // 12*512 float4 = 96 KB

    const int n    = threadIdx.x;        // gates n and n+256
    const int row0 = blockIdx.x * 256;

    u64 wA[40], wB[40];
    {
        const ulonglong2* WA2 = reinterpret_cast<const ulonglong2*>(Wih + n * H);
        const ulonglong2* WB2 = reinterpret_cast<const ulonglong2*>(Wih + (n + 256) * H);
        #pragma unroll
        for (int i = 0; i < 20; i++) {
            ulonglong2 v = WA2[i]; wA[2*i] = v.x; wA[2*i+1] = v.y;
            ulonglong2 u = WB2[i]; wB[2*i] = u.x; wB[2*i+1] = u.y;
        }
    }
    {
        const float4* WtA = reinterpret_cast<const float4*>(Wih + n * H + 80);
        const float4* WtB = reinterpret_cast<const float4*>(Wih + (n + 256) * H + 80);
        #pragma unroll
        for (int j4 = 0; j4 < 12; j4++) {
            Wp4[j4 * 512 + n]       = WtA[j4];
            Wp4[j4 * 512 + n + 256] = WtB[j4];
        }
    }
    const float bnA = bih[n]       + bhh[n];
    const float bnB = bih[n + 256] + bhh[n + 256];

    // load 256-row h tile (8192 float4)
    const float4* HSb = reinterpret_cast<const float4*>(g_HS + (size_t)row0 * H);
    #pragma unroll
    for (int it = 0; it < 32; it++) {
        int i = n + it * 256;
        sh4[i] = HSb[i];
    }
    __syncthreads();

    const ulonglong2* Wv = reinterpret_cast<const ulonglong2*>(Wp4);
    float* Pout = g_P + (size_t)row0 * G;
    #pragma unroll 1
    for (int r = 0; r < 256; r += 4) {
        u64 aA0 = pk2(bnA, 0.f), aA1 = pk2(bnA, 0.f), aA2 = pk2(bnA, 0.f), aA3 = pk2(bnA, 0.f);
        u64 aB0 = pk2(bnB, 0.f), aB1 = pk2(bnB, 0.f), aB2 = pk2(bnB, 0.f), aB3 = pk2(bnB, 0.f);
        const ulonglong2* h0 = reinterpret_cast<const ulonglong2*>(sh4 + (r+0)*32);
        const ulonglong2* h1 = reinterpret_cast<const ulonglong2*>(sh4 + (r+1)*32);
        const ulonglong2* h2 = reinterpret_cast<const ulonglong2*>(sh4 + (r+2)*32);
        const ulonglong2* h3 = reinterpret_cast<const ulonglong2*>(sh4 + (r+3)*32);
        #pragma unroll
        for (int j = 0; j < 20; j++) {
            ulonglong2 a = h0[j], b = h1[j], c = h2[j], d = h3[j];
            u64 wa = wA[2*j], wb = wA[2*j+1], wc = wB[2*j], wd = wB[2*j+1];
            aA0 = ffma2(a.x, wa, aA0); aA0 = ffma2(a.y, wb, aA0);
            aA1 = ffma2(b.x, wa, aA1); aA1 = ffma2(b.y, wb, aA1);
            aA2 = ffma2(c.x, wa, aA2); aA2 = ffma2(c.y, wb, aA2);
            aA3 = ffma2(d.x, wa, aA3); aA3 = ffma2(d.y, wb, aA3);
            aB0 = ffma2(a.x, wc, aB0); aB0 = ffma2(a.y, wd, aB0);
            aB1 = ffma2(b.x, wc, aB1); aB1 = ffma2(b.y, wd, aB1);
            aB2 = ffma2(c.x, wc, aB2); aB2 = ffma2(c.y, wd, aB2);
            aB3 = ffma2(d.x, wc, aB3); aB3 = ffma2(d.y, wd, aB3);
        }
        #pragma unroll
        for (int j4 = 0; j4 < 12; j4++) {
            ulonglong2 wvA = Wv[j4 * 512 + n];
            ulonglong2 wvB = Wv[j4 * 512 + n + 256];
            ulonglong2 a = h0[20 + j4], b = h1[20 + j4], c = h2[20 + j4], d = h3[20 + j4];
            aA0 = ffma2(a.x, wvA.x, aA0); aA0 = ffma2(a.y, wvA.y, aA0);
            aA1 = ffma2(b.x, wvA.x, aA1); aA1 = ffma2(b.y, wvA.y, aA1);
            aA2 = ffma2(c.x, wvA.x, aA2); aA2 = ffma2(c.y, wvA.y, aA2);
            aA3 = ffma2(d.x, wvA.x, aA3); aA3 = ffma2(d.y, wvA.y, aA3);
            aB0 = ffma2(a.x, wvB.x, aB0); aB0 = ffma2(a.y, wvB.y, aB0);
            aB1 = ffma2(b.x, wvB.x, aB1); aB1 = ffma2(b.y, wvB.y, aB1);
            aB2 = ffma2(c.x, wvB.x, aB2); aB2 = ffma2(c.y, wvB.y, aB2);
            aB3 = ffma2(d.x, wvB.x, aB3); aB3 = ffma2(d.y, wvB.y, aB3);
        }
        Pout[(size_t)(r+0) * G + n] = hsum2(aA0);
        Pout[(size_t)(r+1) * G + n] = hsum2(aA1);
        Pout[(size_t)(r+2) * G + n] = hsum2(aA2);
        Pout[(size_t)(r+3) * G + n] = hsum2(aA3);
        Pout[(size_t)(r+0) * G + n + 256] = hsum2(aB0);
        Pout[(size_t)(r+1) * G + n + 256] = hsum2(aB1);
        Pout[(size_t)(r+2) * G + n + 256] = hsum2(aB2);
        Pout[(size_t)(r+3) * G + n + 256] = hsum2(aB3);
    }
}

// ============================================================================
// scan v3: persistent LSTM recurrence, 128 blocks x 4 batch rows, 256 threads.
// Warp-local gate layout: warp w, lane p<16 owns gate rows (j, j+128)=(i,f),
// lane p>=16 owns (j+256, j+384)=(g,o), j = 16w + (p&15). Gate exchange via
// 4 shfl.xor 16 -> no gate smem, ONE barrier/step. Lanes<16 update batch
// rows {0,1}; lanes>=16 rows {2,3}. Weights: k<80 regs, k in [80,128) smem.
// ============================================================================
__global__ void __launch_bounds__(256, 1)
scan_kernel(const float* __restrict__ Whh, int write_hs, int write_hl)
{
    extern __shared__ char sm[];
    float4* Wsm4 = reinterpret_cast<float4*>(sm);            // 12*512*16B = 96 KB
    float*  h_sm = reinterpret_cast<float*>(sm + 98304);     // 4*128 = 2 KB

    const int tid  = threadIdx.x;
    const int lane = tid & 31;
    const int wrp  = tid >> 5;
    const int j    = (wrp << 4) + (lane & 15);   // hidden column index [0,128)
    const int gsel = lane >> 4;                  // 0: owns (i,f); 1: owns (g,o)
    const int rowA = j + gsel * 256;             // i[j] or g[j]
    const int rowB = rowA + 128;                 // f[j] or o[j]
    const int rb   = gsel * 2;                   // owned batch rows rb, rb+1
    const int b0   = blockIdx.x * 4;

    // register weights: k<80 for both gate rows
    u64 wA[40], wB[40];
    {
        const ulonglong2* WA2 = reinterpret_cast<const ulonglong2*>(Whh + rowA * H);
        const ulonglong2* WB2 = reinterpret_cast<const ulonglong2*>(Whh + rowB * H);
        #pragma unroll
        for (int i = 0; i < 20; i++) {
            ulonglong2 v = WA2[i]; wA[2*i] = v.x; wA[2*i+1] = v.y;
            ulonglong2 u = WB2[i]; wB[2*i] = u.x; wB[2*i+1] = u.y;
        }
    }
    // smem weights: k in [80,128), slots tid and tid+256
    {
        const float4* WtA = reinterpret_cast<const float4*>(Whh + rowA * H + 80);
        const float4* WtB = reinterpret_cast<const float4*>(Whh + rowB * H + 80);
        #pragma unroll
        for (int j4 = 0; j4 < 12; j4++) {
            Wsm4[j4 * 512 + tid]       = WtA[j4];
            Wsm4[j4 * 512 + tid + 256] = WtB[j4];
        }
    }
    h_sm[tid] = 0.f; h_sm[tid + 256] = 0.f;
    float c0s = 0.f, c1s = 0.f;      // cell states for rows rb, rb+1 (column j)
    __syncthreads();

    const float* PA = g_P + (size_t)b0 * G + rowA;
    const float* PB = g_P + (size_t)b0 * G + rowB;
    float pA0 = PA[0*G], pA1 = PA[1*G], pA2 = PA[2*G], pA3 = PA[3*G];
    float pB0 = PB[0*G], pB1 = PB[1*G], pB2 = PB[2*G], pB3 = PB[3*G];

    const ulonglong2* Wv = reinterpret_cast<const ulonglong2*>(Wsm4);
    const ulonglong2* hv = reinterpret_cast<const ulonglong2*>(h_sm); // 32 per row

    #pragma unroll 1
    for (int t = 0; t < T_STEPS; t++) {
        u64 aA0 = pk2(pA0, 0.f), aA1 = pk2(pA1, 0.f), aA2 = pk2(pA2, 0.f), aA3 = pk2(pA3, 0.f);
        u64 aB0 = pk2(pB0, 0.f), aB1 = pk2(pB1, 0.f), aB2 = pk2(pB2, 0.f), aB3 = pk2(pB3, 0.f);
        if (t + 1 < T_STEPS) {   // prefetch next step's x-projection
            const float* QA = PA + (size_t)(t + 1) * BATCH * G;
            const float* QB = PB + (size_t)(t + 1) * BATCH * G;
            pA0 = QA[0*G]; pA1 = QA[1*G]; pA2 = QA[2*G]; pA3 = QA[3*G];
            pB0 = QB[0*G]; pB1 = QB[1*G]; pB2 = QB[2*G]; pB3 = QB[3*G];
        }

        // k < 80: register weights
        #pragma unroll
        for (int jl = 0; jl < 20; jl++) {
            ulonglong2 ha = hv[0*32 + jl], hb = hv[1*32 + jl];
            ulonglong2 hc = hv[2*32 + jl], hd = hv[3*32 + jl];
            u64 wa = wA[2*jl], wb = wA[2*jl+1], wc = wB[2*jl], wd = wB[2*jl+1];
            aA0 = ffma2(ha.x, wa, aA0); aA0 = ffma2(ha.y, wb, aA0);
            aA1 = ffma2(hb.x, wa, aA1); aA1 = ffma2(hb.y, wb, aA1);
            aA2 = ffma2(hc.x, wa, aA2); aA2 = ffma2(hc.y, wb, aA2);
            aA3 = ffma2(hd.x, wa, aA3); aA3 = ffma2(hd.y, wb, aA3);
            aB0 = ffma2(ha.x, wc, aB0); aB0 = ffma2(ha.y, wd, aB0);
            aB1 = ffma2(hb.x, wc, aB1); aB1 = ffma2(hb.y, wd, aB1);
            aB2 = ffma2(hc.x, wc, aB2); aB2 = ffma2(hc.y, wd, aB2);
            aB3 = ffma2(hd.x, wc, aB3); aB3 = ffma2(hd.y, wd, aB3);
        }
        // k in [80,128): smem weights
        #pragma unroll
        for (int j4 = 0; j4 < 12; j4++) {
            ulonglong2 wvA = Wv[j4 * 512 + tid];
            ulonglong2 wvB = Wv[j4 * 512 + tid + 256];
            ulonglong2 ha = hv[0*32 + 20 + j4], hb = hv[1*32 + 20 + j4];
            ulonglong2 hc = hv[2*32 + 20 + j4], hd = hv[3*32 + 20 + j4];
            aA0 = ffma2(ha.x, wvA.x, aA0); aA0 = ffma2(ha.y, wvA.y, aA0);
            aA1 = ffma2(hb.x, wvA.x, aA1); aA1 = ffma2(hb.y, wvA.y, aA1);
            aA2 = ffma2(hc.x, wvA.x, aA2); aA2 = ffma2(hc.y, wvA.y, aA2);
            aA3 = ffma2(hd.x, wvA.x, aA3); aA3 = ffma2(hd.y, wvA.y, aA3);
            aB0 = ffma2(ha.x, wvB.x, aB0); aB0 = ffma2(ha.y, wvB.y, aB0);
            aB1 = ffma2(hb.x, wvB.x, aB1); aB1 = ffma2(hb.y, wvB.y, aB1);
            aB2 = ffma2(hc.x, wvB.x, aB2); aB2 = ffma2(hc.y, wvB.y, aB2);
            aB3 = ffma2(hd.x, wvB.x, aB3); aB3 = ffma2(hd.y, wvB.y, aB3);
        }
        const float gA0 = hsum2(aA0), gA1 = hsum2(aA1), gA2 = hsum2(aA2), gA3 = hsum2(aA3);
        const float gB0 = hsum2(aB0), gB1 = hsum2(aB1), gB2 = hsum2(aB2), gB3 = hsum2(aB3);

        // warp-level gate exchange between lanes p and p^16 (4 shuffles)
        const float s0 = __shfl_xor_sync(0xffffffffu, gsel ? gA0 : gA2, 16);
        const float s1 = __shfl_xor_sync(0xffffffffu, gsel ? gA1 : gA3, 16);
        const float s2 = __shfl_xor_sync(0xffffffffu, gsel ? gB0 : gB2, 16);
        const float s3 = __shfl_xor_sync(0xffffffffu, gsel ? gB1 : gB3, 16);
        // lanes<16 (gsel=0): rows 0,1: i=gA*, f=gB*, g=s*, o=s*
        // lanes>=16 (gsel=1): rows 2,3: i=s*, f=s*, g=gA*, o=gB*
        const float i0 = gsel ? s0  : gA0;
        const float f0 = gsel ? s2  : gB0;
        const float g0 = gsel ? gA2 : s0;
        const float o0 = gsel ? gB2 : s2;
        const float i1 = gsel ? s1  : gA1;
        const float f1 = gsel ? s3  : gB1;
        const float g1 = gsel ? gA3 : s1;
        const float o1 = gsel ? gB3 : s3;

        c0s = sigm(f0) * c0s + sigm(i0) * tanh_f(g0);
        const float hn0 = sigm(o0) * tanh_f(c0s);
        c1s = sigm(f1) * c1s + sigm(i1) * tanh_f(g1);
        const float hn1 = sigm(o1) * tanh_f(c1s);

        h_sm[(rb    ) * H + j] = hn0;
        h_sm[(rb + 1) * H + j] = hn1;
        if (write_hs) {
            g_HS[((size_t)t * BATCH + b0 + rb    ) * H + j] = hn0;
            g_HS[((size_t)t * BATCH + b0 + rb + 1) * H + j] = hn1;
        }
        if (write_hl && t == T_STEPS - 1) {
            g_HL[(b0 + rb    ) * H + j] = hn0;
            g_HL[(b0 + rb + 1) * H + j] = hn1;
        }
        __syncthreads();   // single barrier per step
    }
}

// ============================================================================
// head: y[b] = fc2_w . relu(fc1_w @ h_last[b] + fc1_b) + fc2_b
// ============================================================================
__global__ void __launch_bounds__(128)
head_kernel(const float* __restrict__ fc1w, const float* __restrict__ fc1b,
            const float* __restrict__ fc2w, const float* __restrict__ fc2b,
            float* __restrict__ out)
{
    __shared__ float hs[H];
    __shared__ float red[H];
    const int b = blockIdx.x, j = threadIdx.x;
    hs[j] = g_HL[b * H + j];
    __syncthreads();

    float a = fc1b[j];
    const float4* wr = reinterpret_cast<const float4*>(fc1w + j * H);
    const float4* hv = reinterpret_cast<const float4*>(hs);
    #pragma unroll
    for (int k = 0; k < 32; k++) {
        float4 wv = wr[k], h4 = hv[k];
        a = fmaf(wv.x, h4.x, a); a = fmaf(wv.y, h4.y, a);
        a = fmaf(wv.z, h4.z, a); a = fmaf(wv.w, h4.w, a);
    }
    a = fmaxf(a, 0.f) * fc2w[j];
    red[j] = a;
    __syncthreads();
    #pragma unroll
    for (int s = 64; s > 0; s >>= 1) {
        if (j < s) red[j] += red[j + s];
        __syncthreads();
    }
    if (j == 0) out[b] = red[0] + fc2b[0];
}

// ============================================================================
extern "C" void kernel_launch(void* const* d_in, const int* in_sizes, int n_in,
                              void* d_out, int out_size)
{
    const float* x    = (const float*)d_in[0];
    const float* Wih0 = (const float*)d_in[1];
    const float* Whh0 = (const float*)d_in[2];
    const float* bih0 = (const float*)d_in[3];
    const float* bhh0 = (const float*)d_in[4];
    const float* Wih1 = (const float*)d_in[5];
    const float* Whh1 = (const float*)d_in[6];
    const float* bih1 = (const float*)d_in[7];
    const float* bhh1 = (const float*)d_in[8];
    const float* fc1w = (const float*)d_in[9];
    const float* fc1b = (const float*)d_in[10];
    const float* fc2w = (const float*)d_in[11];
    const float* fc2b = (const float*)d_in[12];
    float* out = (float*)d_out;

    const int SCAN_SMEM  = 98304 + 2048;            // 100352 B
    const int PROJ1_SMEM = 131072 + 98304;          // 229376 B
    cudaFuncSetAttribute(scan_kernel,  cudaFuncAttributeMaxDynamicSharedMemorySize, SCAN_SMEM);
    cudaFuncSetAttribute(proj1_kernel, cudaFuncAttributeMaxDynamicSharedMemorySize, PROJ1_SMEM);

    // layer 0
    proj0_kernel<<<(T_STEPS * BATCH) / 128, 256>>>(x, Wih0, bih0, bhh0);
    scan_kernel<<<BATCH / 4, 256, SCAN_SMEM>>>(Whh0, /*write_hs=*/1, /*write_hl=*/0);
    // layer 1
    proj1_kernel<<<(T_STEPS * BATCH) / 256, 256, PROJ1_SMEM>>>(Wih1, bih1, bhh1);
    scan_kernel<<<BATCH / 4, 256, SCAN_SMEM>>>(Whh1, /*write_hs=*/0, /*write_hl=*/1);
    // FC head
    head_kernel<<<BATCH, 128>>>(fc1w, fc1b, fc2w, fc2b, out);
}

// round 15
// speedup vs baseline: 1.3911x; 1.3911x over previous
#include <cuda_runtime.h>

// Problem constants
#define T_STEPS 512
#define BATCH   512
#define IN0     64
#define H       128
#define G       512   // 4*H

// Scratch (rules: no cudaMalloc -> __device__ globals)
__device__ float g_P [(size_t)T_STEPS * BATCH * G];   // 512 MB, reused for both layers
__device__ float g_HS[(size_t)T_STEPS * BATCH * H];   // 128 MB, layer-0 hidden states
__device__ float g_HL[BATCH * H];                     // layer-1 last hidden state

typedef unsigned long long u64;

// ---- packed fp32x2 helpers ----
__device__ __forceinline__ u64 ffma2(u64 a, u64 b, u64 c) {
    u64 d;
    asm("fma.rn.f32x2 %0, %1, %2, %3;" : "=l"(d) : "l"(a), "l"(b), "l"(c));
    return d;
}
__device__ __forceinline__ u64 pk2(float lo, float hi) {
    u64 d; unsigned a = __float_as_uint(lo), b = __float_as_uint(hi);
    asm("mov.b64 %0, {%1, %2};" : "=l"(d) : "r"(a), "r"(b));
    return d;
}
__device__ __forceinline__ float hsum2(u64 v) {
    unsigned a, b;
    asm("mov.b64 {%0, %1}, %2;" : "=r"(a), "=r"(b) : "l"(v));
    return __uint_as_float(a) + __uint_as_float(b);
}

// ---- fast activations (MUFU EX2+RCP, ~1e-6 rel err) ----
__device__ __forceinline__ float sigm(float x) {
    return __fdividef(1.f, 1.f + __expf(-x));
}
__device__ __forceinline__ float tanh_f(float x) {
    return 2.f * sigm(2.f * x) - 1.f;
}

// ============================================================================
// proj0 (R9/R11 v1, measured-good): 512 threads, 1 gate/thread, weights
// (64 floats = 32 u64) in registers; x rows broadcast from smem.
// ============================================================================
__global__ void __launch_bounds__(512, 1)
proj0_kernel(const float* __restrict__ x, const float* __restrict__ Wih,
             const float* __restrict__ bih, const float* __restrict__ bhh)
{
    __shared__ float4 xs4[128 * 16];   // 128 rows x 64 floats = 32 KB
    const int n    = threadIdx.x;
    const int row0 = blockIdx.x * 128;
    const int t    = row0 >> 9;        // 128 | 512 -> t constant per block
    const int b0   = row0 & 511;

    u64 w[32];
    {
        const ulonglong2* W2 = reinterpret_cast<const ulonglong2*>(Wih + n * IN0);
        #pragma unroll
        for (int i = 0; i < 16; i++) { ulonglong2 v = W2[i]; w[2*i] = v.x; w[2*i+1] = v.y; }
    }
    const float bn = bih[n] + bhh[n];

    #pragma unroll
    for (int it = 0; it < 4; it++) {
        int i = n + it * 512;
        int r = i >> 4, c = i & 15;
        xs4[i] = reinterpret_cast<const float4*>(
                     x + ((size_t)(b0 + r) * T_STEPS + t) * IN0)[c];
    }
    __syncthreads();

    float* Pout = g_P + (size_t)row0 * G + n;
    #pragma unroll 1
    for (int r = 0; r < 128; r += 2) {
        u64 acc0 = pk2(bn, 0.f), acc1 = pk2(bn, 0.f);
        const ulonglong2* h0 = reinterpret_cast<const ulonglong2*>(xs4 + (r    ) * 16);
        const ulonglong2* h1 = reinterpret_cast<const ulonglong2*>(xs4 + (r + 1) * 16);
        #pragma unroll
        for (int j = 0; j < 16; j++) {
            ulonglong2 a = h0[j], b = h1[j];
            acc0 = ffma2(a.x, w[2*j],   acc0);
            acc0 = ffma2(a.y, w[2*j+1], acc0);
            acc1 = ffma2(b.x, w[2*j],   acc1);
            acc1 = ffma2(b.y, w[2*j+1], acc1);
        }
        Pout[(size_t)(r    ) * G] = hsum2(acc0);
        Pout[(size_t)(r + 1) * G] = hsum2(acc1);
    }
}

// ============================================================================
// proj1 (R9 style, measured-best): 256 threads, 1 gate/thread, ALL 128 weight
// floats in registers (w[64] u64), 4-row accumulators, 64KB h-tile smem.
// Grid: (2048, 2) — blockIdx.y selects the 256-wide gate half.
// ============================================================================
__global__ void __launch_bounds__(256, 1)
proj1_kernel(const float* __restrict__ Wih,
             const float* __restrict__ bih, const float* __restrict__ bhh)
{
    extern __shared__ float4 sh4[];    // 128 rows x 128 floats = 64 KB
    const int tid  = threadIdx.x;
    const int n    = blockIdx.y * 256 + tid;
    const int row0 = blockIdx.x * 128;

    u64 w[64];
    {
        const ulonglong2* W2 = reinterpret_cast<const ulonglong2*>(Wih + n * H);
        #pragma unroll
        for (int i = 0; i < 32; i++) { ulonglong2 v = W2[i]; w[2*i] = v.x; w[2*i+1] = v.y; }
    }
    const float bn = bih[n] + bhh[n];

    const float4* HSb = reinterpret_cast<const float4*>(g_HS + (size_t)row0 * H);
    #pragma unroll
    for (int it = 0; it < 16; it++) {
        int i = tid + it * 256;        // i in [0, 4096)
        sh4[i] = HSb[i];
    }
    __syncthreads();

    float* Pout = g_P + (size_t)row0 * G + n;
    #pragma unroll 1
    for (int r = 0; r < 128; r += 4) {
        u64 acc0 = pk2(bn, 0.f), acc1 = pk2(bn, 0.f);
        u64 acc2 = pk2(bn, 0.f), acc3 = pk2(bn, 0.f);
        const ulonglong2* h0 = reinterpret_cast<const ulonglong2*>(sh4 + (r+0)*32);
        const ulonglong2* h1 = reinterpret_cast<const ulonglong2*>(sh4 + (r+1)*32);
        const ulonglong2* h2 = reinterpret_cast<const ulonglong2*>(sh4 + (r+2)*32);
        const ulonglong2* h3 = reinterpret_cast<const ulonglong2*>(sh4 + (r+3)*32);
        #pragma unroll
        for (int j = 0; j < 32; j++) {
            ulonglong2 a = h0[j], b = h1[j], c = h2[j], d = h3[j];
            u64 wa = w[2*j], wb = w[2*j+1];
            acc0 = ffma2(a.x, wa, acc0); acc0 = ffma2(a.y, wb, acc0);
            acc1 = ffma2(b.x, wa, acc1); acc1 = ffma2(b.y, wb, acc1);
            acc2 = ffma2(c.x, wa, acc2); acc2 = ffma2(c.y, wb, acc2);
            acc3 = ffma2(d.x, wa, acc3); acc3 = ffma2(d.y, wb, acc3);
        }
        Pout[(size_t)(r+0) * G] = hsum2(acc0);
        Pout[(size_t)(r+1) * G] = hsum2(acc1);
        Pout[(size_t)(r+2) * G] = hsum2(acc2);
        Pout[(size_t)(r+3) * G] = hsum2(acc3);
    }
}

// ============================================================================
// scan v3 (R14, measured 961us, correct): 128 blocks x 4 batch rows, 256 thr.
// Warp-local gate layout: warp w, lane p<16 owns gate rows (j, j+128)=(i,f),
// lane p>=16 owns (j+256, j+384)=(g,o), j = 16w + (p&15). Gate exchange via
// 4 shfl.xor 16 -> no gate smem, ONE barrier/step. Lanes<16 update batch
// rows {0,1}; lanes>=16 rows {2,3}. Weights: k<80 regs, k in [80,128) smem.
// ============================================================================
__global__ void __launch_bounds__(256, 1)
scan_kernel(const float* __restrict__ Whh, int write_hs, int write_hl)
{
    extern __shared__ char sm[];
    float4* Wsm4 = reinterpret_cast<float4*>(sm);            // 12*512*16B = 96 KB
    float*  h_sm = reinterpret_cast<float*>(sm + 98304);     // 4*128 = 2 KB

    const int tid  = threadIdx.x;
    const int lane = tid & 31;
    const int wrp  = tid >> 5;
    const int j    = (wrp << 4) + (lane & 15);   // hidden column index [0,128)
    const int gsel = lane >> 4;                  // 0: owns (i,f); 1: owns (g,o)
    const int rowA = j + gsel * 256;             // i[j] or g[j]
    const int rowB = rowA + 128;                 // f[j] or o[j]
    const int rb   = gsel * 2;                   // owned batch rows rb, rb+1
    const int b0   = blockIdx.x * 4;

    // register weights: k<80 for both gate rows
    u64 wA[40], wB[40];
    {
        const ulonglong2* WA2 = reinterpret_cast<const ulonglong2*>(Whh + rowA * H);
        const ulonglong2* WB2 = reinterpret_cast<const ulonglong2*>(Whh + rowB * H);
        #pragma unroll
        for (int i = 0; i < 20; i++) {
            ulonglong2 v = WA2[i]; wA[2*i] = v.x; wA[2*i+1] = v.y;
            ulonglong2 u = WB2[i]; wB[2*i] = u.x; wB[2*i+1] = u.y;
        }
    }
    // smem weights: k in [80,128), slots tid and tid+256
    {
        const float4* WtA = reinterpret_cast<const float4*>(Whh + rowA * H + 80);
        const float4* WtB = reinterpret_cast<const float4*>(Whh + rowB * H + 80);
        #pragma unroll
        for (int j4 = 0; j4 < 12; j4++) {
            Wsm4[j4 * 512 + tid]       = WtA[j4];
            Wsm4[j4 * 512 + tid + 256] = WtB[j4];
        }
    }
    h_sm[tid] = 0.f; h_sm[tid + 256] = 0.f;
    float c0s = 0.f, c1s = 0.f;      // cell states for rows rb, rb+1 (column j)
    __syncthreads();

    const float* PA = g_P + (size_t)b0 * G + rowA;
    const float* PB = g_P + (size_t)b0 * G + rowB;
    float pA0 = PA[0*G], pA1 = PA[1*G], pA2 = PA[2*G], pA3 = PA[3*G];
    float pB0 = PB[0*G], pB1 = PB[1*G], pB2 = PB[2*G], pB3 = PB[3*G];

    const ulonglong2* Wv = reinterpret_cast<const ulonglong2*>(Wsm4);
    const ulonglong2* hv = reinterpret_cast<const ulonglong2*>(h_sm); // 32 per row

    #pragma unroll 1
    for (int t = 0; t < T_STEPS; t++) {
        u64 aA0 = pk2(pA0, 0.f), aA1 = pk2(pA1, 0.f), aA2 = pk2(pA2, 0.f), aA3 = pk2(pA3, 0.f);
        u64 aB0 = pk2(pB0, 0.f), aB1 = pk2(pB1, 0.f), aB2 = pk2(pB2, 0.f), aB3 = pk2(pB3, 0.f);
        if (t + 1 < T_STEPS) {   // prefetch next step's x-projection
            const float* QA = PA + (size_t)(t + 1) * BATCH * G;
            const float* QB = PB + (size_t)(t + 1) * BATCH * G;
            pA0 = QA[0*G]; pA1 = QA[1*G]; pA2 = QA[2*G]; pA3 = QA[3*G];
            pB0 = QB[0*G]; pB1 = QB[1*G]; pB2 = QB[2*G]; pB3 = QB[3*G];
        }

        // k < 80: register weights
        #pragma unroll
        for (int jl = 0; jl < 20; jl++) {
            ulonglong2 ha = hv[0*32 + jl], hb = hv[1*32 + jl];
            ulonglong2 hc = hv[2*32 + jl], hd = hv[3*32 + jl];
            u64 wa = wA[2*jl], wb = wA[2*jl+1], wc = wB[2*jl], wd = wB[2*jl+1];
            aA0 = ffma2(ha.x, wa, aA0); aA0 = ffma2(ha.y, wb, aA0);
            aA1 = ffma2(hb.x, wa, aA1); aA1 = ffma2(hb.y, wb, aA1);
            aA2 = ffma2(hc.x, wa, aA2); aA2 = ffma2(hc.y, wb, aA2);
            aA3 = ffma2(hd.x, wa, aA3); aA3 = ffma2(hd.y, wb, aA3);
            aB0 = ffma2(ha.x, wc, aB0); aB0 = ffma2(ha.y, wd, aB0);
            aB1 = ffma2(hb.x, wc, aB1); aB1 = ffma2(hb.y, wd, aB1);
            aB2 = ffma2(hc.x, wc, aB2); aB2 = ffma2(hc.y, wd, aB2);
            aB3 = ffma2(hd.x, wc, aB3); aB3 = ffma2(hd.y, wd, aB3);
        }
        // k in [80,128): smem weights
        #pragma unroll
        for (int j4 = 0; j4 < 12; j4++) {
            ulonglong2 wvA = Wv[j4 * 512 + tid];
            ulonglong2 wvB = Wv[j4 * 512 + tid + 256];
            ulonglong2 ha = hv[0*32 + 20 + j4], hb = hv[1*32 + 20 + j4];
            ulonglong2 hc = hv[2*32 + 20 + j4], hd = hv[3*32 + 20 + j4];
            aA0 = ffma2(ha.x, wvA.x, aA0); aA0 = ffma2(ha.y, wvA.y, aA0);
            aA1 = ffma2(hb.x, wvA.x, aA1); aA1 = ffma2(hb.y, wvA.y, aA1);
            aA2 = ffma2(hc.x, wvA.x, aA2); aA2 = ffma2(hc.y, wvA.y, aA2);
            aA3 = ffma2(hd.x, wvA.x, aA3); aA3 = ffma2(hd.y, wvA.y, aA3);
            aB0 = ffma2(ha.x, wvB.x, aB0); aB0 = ffma2(ha.y, wvB.y, aB0);
            aB1 = ffma2(hb.x, wvB.x, aB1); aB1 = ffma2(hb.y, wvB.y, aB1);
            aB2 = ffma2(hc.x, wvB.x, aB2); aB2 = ffma2(hc.y, wvB.y, aB2);
            aB3 = ffma2(hd.x, wvB.x, aB3); aB3 = ffma2(hd.y, wvB.y, aB3);
        }
        const float gA0 = hsum2(aA0), gA1 = hsum2(aA1), gA2 = hsum2(aA2), gA3 = hsum2(aA3);
        const float gB0 = hsum2(aB0), gB1 = hsum2(aB1), gB2 = hsum2(aB2), gB3 = hsum2(aB3);

        // warp-level gate exchange between lanes p and p^16 (4 shuffles)
        const float s0 = __shfl_xor_sync(0xffffffffu, gsel ? gA0 : gA2, 16);
        const float s1 = __shfl_xor_sync(0xffffffffu, gsel ? gA1 : gA3, 16);
        const float s2 = __shfl_xor_sync(0xffffffffu, gsel ? gB0 : gB2, 16);
        const float s3 = __shfl_xor_sync(0xffffffffu, gsel ? gB1 : gB3, 16);
        // lanes<16 (gsel=0): rows 0,1: i=gA*, f=gB*, g=s*, o=s*
        // lanes>=16 (gsel=1): rows 2,3: i=s*, f=s*, g=gA*, o=gB*
        const float i0 = gsel ? s0  : gA0;
        const float f0 = gsel ? s2  : gB0;
        const float g0 = gsel ? gA2 : s0;
        const float o0 = gsel ? gB2 : s2;
        const float i1 = gsel ? s1  : gA1;
        const float f1 = gsel ? s3  : gB1;
        const float g1 = gsel ? gA3 : s1;
        const float o1 = gsel ? gB3 : s3;

        c0s = sigm(f0) * c0s + sigm(i0) * tanh_f(g0);
        const float hn0 = sigm(o0) * tanh_f(c0s);
        c1s = sigm(f1) * c1s + sigm(i1) * tanh_f(g1);
        const float hn1 = sigm(o1) * tanh_f(c1s);

        h_sm[(rb    ) * H + j] = hn0;
        h_sm[(rb + 1) * H + j] = hn1;
        if (write_hs) {
            g_HS[((size_t)t * BATCH + b0 + rb    ) * H + j] = hn0;
            g_HS[((size_t)t * BATCH + b0 + rb + 1) * H + j] = hn1;
        }
        if (write_hl && t == T_STEPS - 1) {
            g_HL[(b0 + rb    ) * H + j] = hn0;
            g_HL[(b0 + rb + 1) * H + j] = hn1;
        }
        __syncthreads();   // single barrier per step
    }
}

// ============================================================================
// head: y[b] = fc2_w . relu(fc1_w @ h_last[b] + fc1_b) + fc2_b
// ============================================================================
__global__ void __launch_bounds__(128)
head_kernel(const float* __restrict__ fc1w, const float* __restrict__ fc1b,
            const float* __restrict__ fc2w, const float* __restrict__ fc2b,
            float* __restrict__ out)
{
    __shared__ float hs[H];
    __shared__ float red[H];
    const int b = blockIdx.x, j = threadIdx.x;
    hs[j] = g_HL[b * H + j];
    __syncthreads();

    float a = fc1b[j];
    const float4* wr = reinterpret_cast<const float4*>(fc1w + j * H);
    const float4* hv = reinterpret_cast<const float4*>(hs);
    #pragma unroll
    for (int k = 0; k < 32; k++) {
        float4 wv = wr[k], h4 = hv[k];
        a = fmaf(wv.x, h4.x, a); a = fmaf(wv.y, h4.y, a);
        a = fmaf(wv.z, h4.z, a); a = fmaf(wv.w, h4.w, a);
    }
    a = fmaxf(a, 0.f) * fc2w[j];
    red[j] = a;
    __syncthreads();
    #pragma unroll
    for (int s = 64; s > 0; s >>= 1) {
        if (j < s) red[j] += red[j + s];
        __syncthreads();
    }
    if (j == 0) out[b] = red[0] + fc2b[0];
}

// ============================================================================
extern "C" void kernel_launch(void* const* d_in, const int* in_sizes, int n_in,
                              void* d_out, int out_size)
{
    const float* x    = (const float*)d_in[0];
    const float* Wih0 = (const float*)d_in[1];
    const float* Whh0 = (const float*)d_in[2];
    const float* bih0 = (const float*)d_in[3];
    const float* bhh0 = (const float*)d_in[4];
    const float* Wih1 = (const float*)d_in[5];
    const float* Whh1 = (const float*)d_in[6];
    const float* bih1 = (const float*)d_in[7];
    const float* bhh1 = (const float*)d_in[8];
    const float* fc1w = (const float*)d_in[9];
    const float* fc1b = (const float*)d_in[10];
    const float* fc2w = (const float*)d_in[11];
    const float* fc2b = (const float*)d_in[12];
    float* out = (float*)d_out;

    const int SCAN_SMEM  = 98304 + 2048;   // 100352 B
    const int PROJ1_SMEM = 65536;          // 64 KB h-tile
    cudaFuncSetAttribute(scan_kernel,  cudaFuncAttributeMaxDynamicSharedMemorySize, SCAN_SMEM);
    cudaFuncSetAttribute(proj1_kernel, cudaFuncAttributeMaxDynamicSharedMemorySize, PROJ1_SMEM);

    // layer 0
    proj0_kernel<<<(T_STEPS * BATCH) / 128, 512>>>(x, Wih0, bih0, bhh0);
    scan_kernel<<<BATCH / 4, 256, SCAN_SMEM>>>(Whh0, /*write_hs=*/1, /*write_hl=*/0);
    // layer 1
    dim3 g1((T_STEPS * BATCH) / 128, 2);
    proj1_kernel<<<g1, 256, PROJ1_SMEM>>>(Wih1, bih1, bhh1);
    scan_kernel<<<BATCH / 4, 256, SCAN_SMEM>>>(Whh1, /*write_hs=*/0, /*write_hl=*/1);
    // FC head
    head_kernel<<<BATCH, 128>>>(fc1w, fc1b, fc2w, fc2b, out);
}